// round 1
// baseline (speedup 1.0000x reference)
#include <cuda_runtime.h>
#include <math.h>

#define B_   4
#define SQ_  2048
#define SK_  2048
#define E_   1024
#define H_   16
#define D_   64
#define M_TOT (B_ * SQ_)                       // 8192
#define OUT_ELEMS (B_ * SQ_ * E_)              // 8388608
#define ATT_ELEMS ((long long)B_ * H_ * SQ_ * SK_)  // 268435456

// Scratch (static device arrays; runtime allocation is forbidden)
__device__ float g_Q[B_ * H_ * SQ_ * D_];      // [b][h][sq][d], pre-scaled by 1/sqrt(D)
__device__ float g_K[B_ * H_ * SK_ * D_];      // [b][h][sk][d]
__device__ float g_V[B_ * H_ * SK_ * D_];      // [b][h][sk][d]
__device__ float g_AO[B_ * SQ_ * E_];          // merged-head attention output
__device__ float g_attn_fb[ATT_ELEMS];         // fallback if d_out doesn't hold attn

// ----------------------------------------------------------------------------
// NT SGEMM: C = A[M,K] * B[N,K]^T (+bias) — both operands K-major (row-major).
// Tile 128x128xBK8, 256 threads, 8x8 per-thread microkernel.
// MODE 0: write C row-major [M,N] (per-z offset sC).
// MODE 1: write head-split: m=(b,s), n=(h,d) -> C[((b*H+h)*S + s)*D + d], *scale.
// Batched over blockIdx.z with element strides sA,sB,sC.
// Requires M%128==0, N%128==0, K%8==0 (true for all uses here).
// ----------------------------------------------------------------------------
template <int MODE>
__launch_bounds__(256)
__global__ void sgemm_nt(const float* __restrict__ A, const float* __restrict__ Bm,
                         const float* __restrict__ bias, float* __restrict__ C,
                         int M, int N, int K, float scale,
                         long long sA, long long sB, long long sC)
{
    const float* Ap = A + (long long)blockIdx.z * sA;
    const float* Bp = Bm + (long long)blockIdx.z * sB;
    float* Cp = C + (long long)blockIdx.z * sC;

    __shared__ float As[8][128];
    __shared__ float Bs[8][128];

    const int tid = threadIdx.x;
    const int tx = tid & 15;        // 16 thread-cols
    const int ty = tid >> 4;        // 16 thread-rows
    const int row0 = blockIdx.y * 128;
    const int col0 = blockIdx.x * 128;

    const int lr = tid >> 1;        // 0..127 (tile row loaded by this thread)
    const int lk = (tid & 1) * 4;   // 0 or 4 (k offset, float4)

    float acc[8][8];
#pragma unroll
    for (int i = 0; i < 8; i++)
#pragma unroll
        for (int j = 0; j < 8; j++) acc[i][j] = 0.f;

    for (int k0 = 0; k0 < K; k0 += 8) {
        float4 av = *(const float4*)(Ap + (long long)(row0 + lr) * K + k0 + lk);
        float4 bv = *(const float4*)(Bp + (long long)(col0 + lr) * K + k0 + lk);
        As[lk + 0][lr] = av.x; As[lk + 1][lr] = av.y;
        As[lk + 2][lr] = av.z; As[lk + 3][lr] = av.w;
        Bs[lk + 0][lr] = bv.x; Bs[lk + 1][lr] = bv.y;
        Bs[lk + 2][lr] = bv.z; Bs[lk + 3][lr] = bv.w;
        __syncthreads();

#pragma unroll
        for (int kk = 0; kk < 8; kk++) {
            float a[8], b[8];
            float4 a0 = *(const float4*)&As[kk][ty * 8];
            float4 a1 = *(const float4*)&As[kk][ty * 8 + 4];
            float4 b0 = *(const float4*)&Bs[kk][tx * 8];
            float4 b1 = *(const float4*)&Bs[kk][tx * 8 + 4];
            a[0] = a0.x; a[1] = a0.y; a[2] = a0.z; a[3] = a0.w;
            a[4] = a1.x; a[5] = a1.y; a[6] = a1.z; a[7] = a1.w;
            b[0] = b0.x; b[1] = b0.y; b[2] = b0.z; b[3] = b0.w;
            b[4] = b1.x; b[5] = b1.y; b[6] = b1.z; b[7] = b1.w;
#pragma unroll
            for (int i = 0; i < 8; i++)
#pragma unroll
                for (int j = 0; j < 8; j++) acc[i][j] = fmaf(a[i], b[j], acc[i][j]);
        }
        __syncthreads();
    }

#pragma unroll
    for (int i = 0; i < 8; i++) {
        const int m = row0 + ty * 8 + i;
#pragma unroll
        for (int j = 0; j < 8; j++) {
            const int n = col0 + tx * 8 + j;
            float v = acc[i][j] + (bias ? bias[n] : 0.f);
            if (MODE == 0) {
                Cp[(long long)m * N + n] = v;
            } else {
                const int bb = m >> 11;          // / SQ_ (2048)
                const int s  = m & (SQ_ - 1);
                const int h  = n >> 6;           // / D_
                const int d  = n & (D_ - 1);
                Cp[(((long long)(bb * H_ + h) * SQ_) + s) * D_ + d] = v * scale;
            }
        }
    }
}

// ----------------------------------------------------------------------------
// Row softmax in place. One block (256 threads) per row of length SK_=2048.
// ----------------------------------------------------------------------------
__launch_bounds__(256)
__global__ void softmax_rows(float* __restrict__ P)
{
    float* p = P + (long long)blockIdx.x * SK_;
    const int tid = threadIdx.x;
    const int lane = tid & 31, wid = tid >> 5;
    __shared__ float red[8];
    __shared__ float bc;

    float x[8];
    float m = -INFINITY;
#pragma unroll
    for (int i = 0; i < 8; i++) {
        x[i] = p[tid + 256 * i];
        m = fmaxf(m, x[i]);
    }
#pragma unroll
    for (int o = 16; o > 0; o >>= 1) m = fmaxf(m, __shfl_xor_sync(0xffffffffu, m, o));
    if (lane == 0) red[wid] = m;
    __syncthreads();
    if (tid == 0) {
        float mm = red[0];
#pragma unroll
        for (int w = 1; w < 8; w++) mm = fmaxf(mm, red[w]);
        bc = mm;
    }
    __syncthreads();
    m = bc;

    float s = 0.f;
    float e[8];
#pragma unroll
    for (int i = 0; i < 8; i++) { e[i] = __expf(x[i] - m); s += e[i]; }
#pragma unroll
    for (int o = 16; o > 0; o >>= 1) s += __shfl_xor_sync(0xffffffffu, s, o);
    __syncthreads();          // red[] reuse
    if (lane == 0) red[wid] = s;
    __syncthreads();
    if (tid == 0) {
        float ss = 0.f;
#pragma unroll
        for (int w = 0; w < 8; w++) ss += red[w];
        bc = 1.f / ss;
    }
    __syncthreads();
    const float inv = bc;
#pragma unroll
    for (int i = 0; i < 8; i++) p[tid + 256 * i] = e[i] * inv;
}

// ----------------------------------------------------------------------------
// PV: O[b][sq][h*64+d] = sum_k P[bh][sq][k] * V[bh][k][d].  NN GEMM, N=64.
// Block: 64 query rows x 64 d, 256 threads, 4x4 per thread, BK=32.
// ----------------------------------------------------------------------------
__launch_bounds__(256)
__global__ void pv_kernel(const float* __restrict__ P, const float* __restrict__ V,
                          float* __restrict__ O)
{
    const int bh = blockIdx.z;
    const int b = bh >> 4, h = bh & 15;
    const float* Pp = P + (long long)bh * SQ_ * SK_;
    const float* Vp = V + (long long)bh * SK_ * D_;
    const int m0 = blockIdx.x * 64;

    __shared__ float Ps[32][65];   // [k][m], padded
    __shared__ float Vs[32][64];   // [k][n]

    const int tid = threadIdx.x;
    const int tx = tid & 15, ty = tid >> 4;

    float acc[4][4];
#pragma unroll
    for (int i = 0; i < 4; i++)
#pragma unroll
        for (int j = 0; j < 4; j++) acc[i][j] = 0.f;

    for (int k0 = 0; k0 < SK_; k0 += 32) {
        // load P tile: 64 rows x 32 k = 512 float4, 2 per thread
#pragma unroll
        for (int q = 0; q < 2; q++) {
            const int id = tid + 256 * q;
            const int r = id >> 3;            // 0..63
            const int kq = (id & 7) * 4;      // 0..28
            float4 v = *(const float4*)(Pp + (long long)(m0 + r) * SK_ + k0 + kq);
            Ps[kq + 0][r] = v.x; Ps[kq + 1][r] = v.y;
            Ps[kq + 2][r] = v.z; Ps[kq + 3][r] = v.w;
        }
        // load V tile: 32 rows x 64 n = 512 float4, 2 per thread
#pragma unroll
        for (int q = 0; q < 2; q++) {
            const int id = tid + 256 * q;
            const int kr = id >> 4;           // 0..31
            const int nq = (id & 15) * 4;     // 0..60
            float4 v = *(const float4*)(Vp + (long long)(k0 + kr) * D_ + nq);
            *(float4*)&Vs[kr][nq] = v;
        }
        __syncthreads();

#pragma unroll
        for (int kk = 0; kk < 32; kk++) {
            float a[4], bb[4];
#pragma unroll
            for (int i = 0; i < 4; i++) a[i] = Ps[kk][ty * 4 + i];
            float4 bv = *(const float4*)&Vs[kk][tx * 4];
            bb[0] = bv.x; bb[1] = bv.y; bb[2] = bv.z; bb[3] = bv.w;
#pragma unroll
            for (int i = 0; i < 4; i++)
#pragma unroll
                for (int j = 0; j < 4; j++) acc[i][j] = fmaf(a[i], bb[j], acc[i][j]);
        }
        __syncthreads();
    }

#pragma unroll
    for (int i = 0; i < 4; i++) {
        const int m = m0 + ty * 4 + i;
#pragma unroll
        for (int j = 0; j < 4; j++) {
            const int n = tx * 4 + j;
            O[((long long)(b * SQ_ + m)) * E_ + h * D_ + n] = acc[i][j];
        }
    }
}

// ----------------------------------------------------------------------------
// Launch
// ----------------------------------------------------------------------------
extern "C" void kernel_launch(void* const* d_in, const int* in_sizes, int n_in,
                              void* d_out, int out_size)
{
    const float* query = (const float*)d_in[0];
    const float* key   = (const float*)d_in[1];
    const float* value = (const float*)d_in[2];
    const float* Wq = (const float*)d_in[3];
    const float* bq = (const float*)d_in[4];
    const float* Wk = (const float*)d_in[5];
    const float* bk = (const float*)d_in[6];
    const float* Wv = (const float*)d_in[7];
    const float* bv = (const float*)d_in[8];
    const float* Wo = (const float*)d_in[9];
    const float* bo = (const float*)d_in[10];
    float* out = (float*)d_out;

    float *qp, *kp, *vp, *aop, *fbp;
    cudaGetSymbolAddress((void**)&qp,  g_Q);
    cudaGetSymbolAddress((void**)&kp,  g_K);
    cudaGetSymbolAddress((void**)&vp,  g_V);
    cudaGetSymbolAddress((void**)&aop, g_AO);
    cudaGetSymbolAddress((void**)&fbp, g_attn_fb);

    // Output assumed to be [output (8.4M floats) | attn_weights (268M floats)].
    float* attn = ((long long)out_size >= (long long)OUT_ELEMS + ATT_ELEMS)
                      ? (out + OUT_ELEMS) : fbp;

    const float qscale = 1.0f / sqrtf((float)D_);   // fold 1/sqrt(64) into Q

    dim3 blk(256);
    dim3 gproj(E_ / 128, M_TOT / 128, 1);
    // Projections into head-split layout
    sgemm_nt<1><<<gproj, blk>>>(query, Wq, bq, qp, M_TOT, E_, E_, qscale, 0, 0, 0);
    sgemm_nt<1><<<gproj, blk>>>(key,   Wk, bk, kp, M_TOT, E_, E_, 1.0f,   0, 0, 0);
    sgemm_nt<1><<<gproj, blk>>>(value, Wv, bv, vp, M_TOT, E_, E_, 1.0f,   0, 0, 0);

    // Scores: per (b,h), S = Q * K^T (scale already in Q) -> attn region
    dim3 gsc(SK_ / 128, SQ_ / 128, B_ * H_);
    sgemm_nt<0><<<gsc, blk>>>(qp, kp, nullptr, attn, SQ_, SK_, D_, 1.0f,
                              (long long)SQ_ * D_, (long long)SK_ * D_,
                              (long long)SQ_ * SK_);

    // Softmax in place (writes final attn_weights)
    softmax_rows<<<B_ * H_ * SQ_, 256>>>(attn);

    // attn @ V -> merged-head attn_out
    pv_kernel<<<dim3(SQ_ / 64, 1, B_ * H_), blk>>>(attn, vp, aop);

    // Output projection
    sgemm_nt<0><<<gproj, blk>>>(aop, Wo, bo, out, M_TOT, E_, E_, 1.0f, 0, 0, 0);
}

// round 7
// speedup vs baseline: 3.6154x; 3.6154x over previous
#include <cuda_runtime.h>
#include <math.h>
#include <stdint.h>

#define B_   4
#define SQ_  2048
#define SK_  2048
#define E_   1024
#define H_   16
#define D_   64
#define M_TOT (B_ * SQ_)                       // 8192
#define OUT_ELEMS (B_ * SQ_ * E_)              // 8388608
#define ATT_ELEMS ((long long)B_ * H_ * SQ_ * SK_)  // 268435456

// Scratch (static device arrays; runtime allocation is forbidden)
__device__ float g_Xq[B_ * SQ_ * E_];          // tf32-rounded query
__device__ float g_Xk[B_ * SK_ * E_];          // tf32-rounded key
__device__ float g_Xv[B_ * SK_ * E_];          // tf32-rounded value
__device__ float g_Wqr[E_ * E_];               // tf32-rounded weights
__device__ float g_Wkr[E_ * E_];
__device__ float g_Wvr[E_ * E_];
__device__ float g_Wor[E_ * E_];
__device__ float g_Q[B_ * H_ * SQ_ * D_];      // [bh][s][d], rounded, *1/sqrt(D)
__device__ float g_K[B_ * H_ * SK_ * D_];      // [bh][s][d], rounded
__device__ float g_V[B_ * H_ * SK_ * D_];      // [bh][s][d], rounded
__device__ float g_Vt[B_ * H_ * D_ * SK_];     // [bh][d][s]  (transposed V)
__device__ float g_AO[B_ * SQ_ * E_];          // merged-head attn out, rounded
__device__ float g_attn_fb[ATT_ELEMS];         // fallback attn buffer

// ---------------------------------------------------------------------------
// Helpers (plain sm_103-compatible: mma.sync / ldmatrix / cp.async / cvt)
// ---------------------------------------------------------------------------
__device__ __forceinline__ uint32_t smem_u32(const void* p) {
    uint32_t a;
    asm("{ .reg .u64 t; cvta.to.shared.u64 t, %1; cvt.u32.u64 %0, t; }" : "=r"(a) : "l"(p));
    return a;
}
__device__ __forceinline__ float rnd_tf32(float x) {
    uint32_t u;
    asm("cvt.rna.tf32.f32 %0, %1;" : "=r"(u) : "f"(x));
    return __uint_as_float(u);
}
#define SW128(off) ((off) ^ (((off) >> 3) & 0x70))

#define CP16(dst, src) asm volatile("cp.async.cg.shared.global [%0], [%1], 16;" :: "r"(dst), "l"(src))
#define CP_COMMIT()    asm volatile("cp.async.commit_group;" ::: "memory")

#define LDSM4(r0, r1, r2, r3, addr) \
    asm volatile("ldmatrix.sync.aligned.m8n8.x4.shared.b16 {%0,%1,%2,%3}, [%4];" \
                 : "=r"(r0), "=r"(r1), "=r"(r2), "=r"(r3) : "r"(addr))

__device__ __forceinline__ void mma_tf32(float* d, const uint32_t* a, const uint32_t* b) {
    asm volatile(
        "mma.sync.aligned.m16n8k8.row.col.f32.tf32.tf32.f32 "
        "{%0,%1,%2,%3}, {%4,%5,%6,%7}, {%8,%9}, {%0,%1,%2,%3};"
        : "+f"(d[0]), "+f"(d[1]), "+f"(d[2]), "+f"(d[3])
        : "r"(a[0]), "r"(a[1]), "r"(a[2]), "r"(a[3]), "r"(b[0]), "r"(b[1]));
}

// ---------------------------------------------------------------------------
// Elementwise tf32 rounding (float4 vectorized)
// ---------------------------------------------------------------------------
__global__ void round_tf32_kernel(const float* __restrict__ x, float* __restrict__ y, int n4)
{
    int i = blockIdx.x * blockDim.x + threadIdx.x;
    if (i < n4) {
        float4 v = ((const float4*)x)[i];
        v.x = rnd_tf32(v.x); v.y = rnd_tf32(v.y);
        v.z = rnd_tf32(v.z); v.w = rnd_tf32(v.w);
        ((float4*)y)[i] = v;
    }
}

// ---------------------------------------------------------------------------
// tf32 mma.sync NT GEMM: D[M,N] = A[M,K]*B[N,K]^T (+bias)*scale, K-major both.
// Operands MUST be tf32-pre-rounded (HMMA truncation is then exact).
// Tile 128 x NTILE x 32, 256 threads (8 warps), warp tile (16*MT) x 32,
// fragments via ldmatrix.x4 (b16 view of tf32), SW128 swizzle, cp.async 2-buf.
// EPI: 0 plain [ldc]; 1 head-split; 2 head-merge.  RND: round output to tf32.
// ---------------------------------------------------------------------------
template <int NTILE, int EPI, int RND>
__launch_bounds__(256)
__global__ void gemm_tc(const float* __restrict__ A, const float* __restrict__ Bm,
                        const float* __restrict__ bias, float* __restrict__ C,
                        int K, int lda, int ldb, int ldc, float scale,
                        long long zsA, long long zsB, long long zsC)
{
    constexpr int NWN = NTILE / 32;      // warps along N (4 or 2)
    constexpr int MT  = NWN;             // m-tiles/warp (4 -> 64 rows, 2 -> 32)
    constexpr int WROWS = MT * 16;
    constexpr uint32_t A_BYTES = 128 * 128;        // 128 rows x 32 tf32
    constexpr uint32_t B_BYTES = NTILE * 128;
    constexpr uint32_t BUF = A_BYTES + B_BYTES;

    extern __shared__ char smem[];
    const uint32_t sb = smem_u32(smem);
    const int tid = threadIdx.x, wid = tid >> 5, lane = tid & 31;
    const int wm = wid / NWN, wn = wid % NWN;

    const float* Az = A + (long long)blockIdx.z * zsA;
    const float* Bz = Bm + (long long)blockIdx.z * zsB;
    const int row0 = blockIdx.y * 128;
    const int col0 = blockIdx.x * NTILE;
    const int NC = K >> 5;

    // ---- global -> smem chunk loader (swizzled 16B) ----
    auto load_chunk = [&](int c, int buf) {
        const int k0 = c << 5;
        const uint32_t base = sb + (uint32_t)buf * BUF;
        const float* Ac = Az + (long long)row0 * lda + k0;
#pragma unroll
        for (int i = 0; i < 4; i++) {
            int f = tid + (i << 8);
            int r = f >> 3, c4 = f & 7;
            uint32_t off = (uint32_t)((r << 7) + (c4 << 4));
            CP16(base + SW128(off), Ac + (long long)r * lda + (c4 << 2));
        }
        const float* Bc = Bz + (long long)col0 * ldb + k0;
#pragma unroll
        for (int i = 0; i < NTILE / 32; i++) {
            int f = tid + (i << 8);
            int r = f >> 3, c4 = f & 7;
            uint32_t off = (uint32_t)((r << 7) + (c4 << 4));
            CP16(base + A_BYTES + SW128(off), Bc + (long long)r * ldb + (c4 << 2));
        }
        CP_COMMIT();
    };

    // ---- fragment addressing (ldmatrix row suppliers) ----
    const int q = lane >> 3, r = lane & 7;
    const int a_rr = (q & 1) * 8 + r;      // row within 16-row m-tile
    const int a_cg = q >> 1;               // col-group offset (0/1)
    const int b_pp = q >> 1;               // which ni of the pair
    const int b_cg = q & 1;

    uint32_t a_base[MT]; int a_r7[MT];
#pragma unroll
    for (int mi = 0; mi < MT; mi++) {
        int row = wm * WROWS + mi * 16 + a_rr;
        a_base[mi] = (uint32_t)(row << 7);
        a_r7[mi] = row & 7;
    }
    uint32_t b_base[2]; int b_r7[2];
#pragma unroll
    for (int p = 0; p < 2; p++) {
        int n = wn * 32 + (p * 2 + b_pp) * 8 + r;
        b_base[p] = (uint32_t)(n << 7);
        b_r7[p] = n & 7;
    }

    float acc[MT][4][4];
#pragma unroll
    for (int mi = 0; mi < MT; mi++)
#pragma unroll
        for (int ni = 0; ni < 4; ni++)
#pragma unroll
            for (int j = 0; j < 4; j++) acc[mi][ni][j] = 0.f;

    load_chunk(0, 0);
    for (int c = 0; c < NC; c++) {
        if (c + 1 < NC) {
            load_chunk(c + 1, (c + 1) & 1);
            asm volatile("cp.async.wait_group 1;" ::: "memory");
        } else {
            asm volatile("cp.async.wait_group 0;" ::: "memory");
        }
        __syncthreads();
        const uint32_t sA = sb + (uint32_t)(c & 1) * BUF;
        const uint32_t sBm = sA + A_BYTES;
#pragma unroll
        for (int ks = 0; ks < 4; ks++) {
            uint32_t af[MT][4], bf[2][4];
#pragma unroll
            for (int mi = 0; mi < MT; mi++)
                LDSM4(af[mi][0], af[mi][1], af[mi][2], af[mi][3],
                      sA + a_base[mi] + (uint32_t)((((2 * ks + a_cg) ^ a_r7[mi]) << 4)));
#pragma unroll
            for (int p = 0; p < 2; p++)
                LDSM4(bf[p][0], bf[p][1], bf[p][2], bf[p][3],
                      sBm + b_base[p] + (uint32_t)((((2 * ks + b_cg) ^ b_r7[p]) << 4)));
#pragma unroll
            for (int mi = 0; mi < MT; mi++)
#pragma unroll
                for (int ni = 0; ni < 4; ni++)
                    mma_tf32(acc[mi][ni], af[mi], &bf[ni >> 1][(ni & 1) * 2]);
        }
        __syncthreads();
    }

    // ---- epilogue: float2 per (mi, rh, ni) ----
    float* Cz = C + (long long)blockIdx.z * zsC;
#pragma unroll
    for (int mi = 0; mi < MT; mi++)
#pragma unroll
        for (int rh = 0; rh < 2; rh++) {
            const int m = row0 + wm * WROWS + mi * 16 + (lane >> 2) + rh * 8;
#pragma unroll
            for (int ni = 0; ni < 4; ni++) {
                const int col = col0 + wn * 32 + ni * 8 + (lane & 3) * 2;
                float v0 = acc[mi][ni][rh * 2]     + (bias ? bias[col] : 0.f);
                float v1 = acc[mi][ni][rh * 2 + 1] + (bias ? bias[col + 1] : 0.f);
                v0 *= scale; v1 *= scale;
                if (RND) { v0 = rnd_tf32(v0); v1 = rnd_tf32(v1); }
                float2 o = make_float2(v0, v1);
                if (EPI == 0) {
                    *(float2*)(Cz + (long long)m * ldc + col) = o;
                } else if (EPI == 1) {
                    const int bb = m >> 11, s = m & (SQ_ - 1);
                    const int h = col >> 6, d = col & 63;
                    *(float2*)(C + (((long long)(bb * H_ + h) * SQ_) + s) * D_ + d) = o;
                } else {
                    const int bb = (int)blockIdx.z >> 4, h = (int)blockIdx.z & 15;
                    *(float2*)(C + ((long long)(bb * SQ_ + m)) * E_ + h * D_ + col) = o;
                }
            }
        }
}

// ---------------------------------------------------------------------------
// V transpose per (b,h): [SK, D] -> [D, SK]   (values already rounded)
// ---------------------------------------------------------------------------
__global__ void vtrans(const float* __restrict__ V, float* __restrict__ Vt)
{
    __shared__ float t[32][33];
    const int z = blockIdx.z;
    const float* Vp = V + (long long)z * SK_ * D_;
    float* Tp = Vt + (long long)z * D_ * SK_;
    const int s0 = blockIdx.x * 32, d0 = blockIdx.y * 32;
    const int tx = threadIdx.x, ty = threadIdx.y;   // 32 x 8
#pragma unroll
    for (int i = 0; i < 4; i++)
        t[ty + i * 8][tx] = Vp[(long long)(s0 + ty + i * 8) * D_ + d0 + tx];
    __syncthreads();
#pragma unroll
    for (int i = 0; i < 4; i++)
        Tp[(long long)(d0 + ty + i * 8) * SK_ + s0 + tx] = t[tx][ty + i * 8];
}

// ---------------------------------------------------------------------------
// Row softmax in place; output rounded to tf32 (feeds PV as mma operand)
// ---------------------------------------------------------------------------
__launch_bounds__(256)
__global__ void softmax_rows(float* __restrict__ P)
{
    float* p = P + (long long)blockIdx.x * SK_;
    const int tid = threadIdx.x;
    const int lane = tid & 31, wid = tid >> 5;
    __shared__ float red[8];
    __shared__ float bc;

    float x[8];
    float m = -INFINITY;
#pragma unroll
    for (int i = 0; i < 8; i++) { x[i] = p[tid + 256 * i]; m = fmaxf(m, x[i]); }
#pragma unroll
    for (int o = 16; o > 0; o >>= 1) m = fmaxf(m, __shfl_xor_sync(0xffffffffu, m, o));
    if (lane == 0) red[wid] = m;
    __syncthreads();
    if (tid == 0) {
        float mm = red[0];
#pragma unroll
        for (int w = 1; w < 8; w++) mm = fmaxf(mm, red[w]);
        bc = mm;
    }
    __syncthreads();
    m = bc;

    float s = 0.f, e[8];
#pragma unroll
    for (int i = 0; i < 8; i++) { e[i] = __expf(x[i] - m); s += e[i]; }
#pragma unroll
    for (int o = 16; o > 0; o >>= 1) s += __shfl_xor_sync(0xffffffffu, s, o);
    __syncthreads();
    if (lane == 0) red[wid] = s;
    __syncthreads();
    if (tid == 0) {
        float ss = 0.f;
#pragma unroll
        for (int w = 0; w < 8; w++) ss += red[w];
        bc = 1.f / ss;
    }
    __syncthreads();
    const float inv = bc;
#pragma unroll
    for (int i = 0; i < 8; i++) p[tid + 256 * i] = rnd_tf32(e[i] * inv);
}

// ---------------------------------------------------------------------------
// Launch
// ---------------------------------------------------------------------------
extern "C" void kernel_launch(void* const* d_in, const int* in_sizes, int n_in,
                              void* d_out, int out_size)
{
    const float* query = (const float*)d_in[0];
    const float* key   = (const float*)d_in[1];
    const float* value = (const float*)d_in[2];
    const float* Wq = (const float*)d_in[3];
    const float* bq = (const float*)d_in[4];
    const float* Wk = (const float*)d_in[5];
    const float* bk = (const float*)d_in[6];
    const float* Wv = (const float*)d_in[7];
    const float* bv = (const float*)d_in[8];
    const float* Wo = (const float*)d_in[9];
    const float* bo = (const float*)d_in[10];
    float* out = (float*)d_out;

    float *xq, *xk, *xv, *wqr, *wkr, *wvr, *wor;
    float *qp, *kp, *vp, *vtp, *aop, *fbp;
    cudaGetSymbolAddress((void**)&xq,  g_Xq);
    cudaGetSymbolAddress((void**)&xk,  g_Xk);
    cudaGetSymbolAddress((void**)&xv,  g_Xv);
    cudaGetSymbolAddress((void**)&wqr, g_Wqr);
    cudaGetSymbolAddress((void**)&wkr, g_Wkr);
    cudaGetSymbolAddress((void**)&wvr, g_Wvr);
    cudaGetSymbolAddress((void**)&wor, g_Wor);
    cudaGetSymbolAddress((void**)&qp,  g_Q);
    cudaGetSymbolAddress((void**)&kp,  g_K);
    cudaGetSymbolAddress((void**)&vp,  g_V);
    cudaGetSymbolAddress((void**)&vtp, g_Vt);
    cudaGetSymbolAddress((void**)&aop, g_AO);
    cudaGetSymbolAddress((void**)&fbp, g_attn_fb);

    float* attn = ((long long)out_size >= (long long)OUT_ELEMS + ATT_ELEMS)
                      ? (out + OUT_ELEMS) : fbp;

    const int SMEM_128 = 2 * (16384 + 16384);   // 65536
    const int SMEM_64  = 2 * (16384 + 8192);    // 49152
    cudaFuncSetAttribute(gemm_tc<128, 1, 1>, cudaFuncAttributeMaxDynamicSharedMemorySize, SMEM_128);
    cudaFuncSetAttribute(gemm_tc<128, 0, 0>, cudaFuncAttributeMaxDynamicSharedMemorySize, SMEM_128);
    cudaFuncSetAttribute(gemm_tc<64, 2, 1>,  cudaFuncAttributeMaxDynamicSharedMemorySize, SMEM_64);

    const float qscale = 1.0f / sqrtf((float)D_);
    dim3 blk(256);

    // Pre-round all first-level GEMM operands to tf32
    const int RB = 256;
    round_tf32_kernel<<<(OUT_ELEMS / 4 + RB - 1) / RB, RB>>>(query, xq, OUT_ELEMS / 4);
    round_tf32_kernel<<<(OUT_ELEMS / 4 + RB - 1) / RB, RB>>>(key,   xk, OUT_ELEMS / 4);
    round_tf32_kernel<<<(OUT_ELEMS / 4 + RB - 1) / RB, RB>>>(value, xv, OUT_ELEMS / 4);
    round_tf32_kernel<<<(E_ * E_ / 4 + RB - 1) / RB, RB>>>(Wq, wqr, E_ * E_ / 4);
    round_tf32_kernel<<<(E_ * E_ / 4 + RB - 1) / RB, RB>>>(Wk, wkr, E_ * E_ / 4);
    round_tf32_kernel<<<(E_ * E_ / 4 + RB - 1) / RB, RB>>>(Wv, wvr, E_ * E_ / 4);
    round_tf32_kernel<<<(E_ * E_ / 4 + RB - 1) / RB, RB>>>(Wo, wor, E_ * E_ / 4);

    // Projections (head-split epilogue, outputs rounded for next GEMM level)
    dim3 gproj(E_ / 128, M_TOT / 128, 1);
    gemm_tc<128, 1, 1><<<gproj, blk, SMEM_128>>>(xq, wqr, bq, qp, E_,
                                                 E_, E_, 0, qscale, 0, 0, 0);
    gemm_tc<128, 1, 1><<<gproj, blk, SMEM_128>>>(xk, wkr, bk, kp, E_,
                                                 E_, E_, 0, 1.0f, 0, 0, 0);
    gemm_tc<128, 1, 1><<<gproj, blk, SMEM_128>>>(xv, wvr, bv, vp, E_,
                                                 E_, E_, 0, 1.0f, 0, 0, 0);

    // V transpose -> [bh][d][s]
    vtrans<<<dim3(SK_ / 32, D_ / 32, B_ * H_), dim3(32, 8)>>>(vp, vtp);

    // Scores: per (b,h) S = Q * K^T (scale folded into Q); raw fp32 out
    dim3 gsc(SK_ / 128, SQ_ / 128, B_ * H_);
    gemm_tc<128, 0, 0><<<gsc, blk, SMEM_128>>>(qp, kp, nullptr, attn, D_,
                                               D_, D_, SK_, 1.0f,
                                               (long long)SQ_ * D_, (long long)SK_ * D_,
                                               (long long)SQ_ * SK_);

    // Softmax in place (writes final attn_weights, tf32-rounded)
    softmax_rows<<<B_ * H_ * SQ_, 256>>>(attn);

    // PV: O = P * Vt^T (head-merge epilogue, rounded for final GEMM)
    dim3 gpv(1, SQ_ / 128, B_ * H_);
    gemm_tc<64, 2, 1><<<gpv, blk, SMEM_64>>>(attn, vtp, nullptr, aop, SK_,
                                             SK_, SK_, 0, 1.0f,
                                             (long long)SQ_ * SK_, (long long)D_ * SK_, 0);

    // Output projection (raw fp32 out)
    gemm_tc<128, 0, 0><<<gproj, blk, SMEM_128>>>(aop, wor, bo, out, E_,
                                                 E_, E_, E_, 1.0f, 0, 0, 0);
}